// round 1
// baseline (speedup 1.0000x reference)
#include <cuda_runtime.h>
#include <cuda_bf16.h>
#include <math.h>

// ---------------------------------------------------------------------------
// MoE layer: router top-2 over 8 experts, per-expert MLP 1024->4096 (GELU) ->1000
// Sparse routed compute (gates are exactly 0 off top-2).
// ---------------------------------------------------------------------------

#define BATCH      8192
#define D_MODEL    1024
#define HIDDEN     4096
#define NUM_CLS    1000
#define NUM_EXP    8
#define TOPK       2
#define NPAIR      (BATCH * TOPK)        // 16384
#define MAX_TILES  136                   // 16384/128 + 8 (segment padding)
#define CAP        (MAX_TILES * 128)     // 17408 padded rows

#define BM 128
#define BN 128
#define BK 16

// ---------------- scratch (static __device__, no allocs) -------------------
__device__ float g_h[(size_t)CAP * HIDDEN];     // ~285 MB hidden activations
__device__ float g_gates[BATCH * NUM_EXP];
__device__ int   g_topi[BATCH * TOPK];
__device__ int   g_pairExpert[NPAIR];
__device__ float g_pairGate[NPAIR];
__device__ int   g_counts[NUM_EXP];
__device__ int   g_segbase[NUM_EXP + 1];
__device__ int   g_cursor[NUM_EXP];
__device__ int   g_permToken[CAP];
__device__ int   g_permPair[CAP];
__device__ float g_permGate[CAP];

__device__ __forceinline__ float gelu_exact(float v) {
    return 0.5f * v * (1.0f + erff(v * 0.70710678118654752f));
}

// ---------------- init: zero counts, poison perm arrays --------------------
__global__ void init_kernel() {
    int i = blockIdx.x * blockDim.x + threadIdx.x;
    if (i < CAP) { g_permToken[i] = -1; g_permPair[i] = -1; }
    if (i < NUM_EXP) g_counts[i] = 0;
}

// ---------------- router: one warp per token -------------------------------
__global__ void router_kernel(const float* __restrict__ x,
                              const float* __restrict__ Wg,
                              const float* __restrict__ bg) {
    int gwarp = (blockIdx.x * blockDim.x + threadIdx.x) >> 5;
    int lane  = threadIdx.x & 31;
    if (gwarp >= BATCH) return;
    const float* xr = x + (size_t)gwarp * D_MODEL;

    float acc[NUM_EXP];
#pragma unroll
    for (int e = 0; e < NUM_EXP; e++) acc[e] = 0.f;

    for (int k0 = lane * 4; k0 < D_MODEL; k0 += 128) {
        float4 xv = *(const float4*)(xr + k0);
        const float* xs = (const float*)&xv;
#pragma unroll
        for (int kk = 0; kk < 4; kk++) {
            const float4* wg = (const float4*)(Wg + (size_t)(k0 + kk) * NUM_EXP);
            float4 w0 = wg[0], w1 = wg[1];
            float xk = xs[kk];
            acc[0] += xk * w0.x; acc[1] += xk * w0.y;
            acc[2] += xk * w0.z; acc[3] += xk * w0.w;
            acc[4] += xk * w1.x; acc[5] += xk * w1.y;
            acc[6] += xk * w1.z; acc[7] += xk * w1.w;
        }
    }
#pragma unroll
    for (int off = 16; off; off >>= 1)
#pragma unroll
        for (int e = 0; e < NUM_EXP; e++)
            acc[e] += __shfl_xor_sync(0xFFFFFFFFu, acc[e], off);

    if (lane == 0) {
        float v[NUM_EXP];
#pragma unroll
        for (int e = 0; e < NUM_EXP; e++) v[e] = acc[e] + bg[e];
        // top-1 (strict > keeps lowest index on tie, matching jax top_k)
        int i1 = 0;
#pragma unroll
        for (int e = 1; e < NUM_EXP; e++) if (v[e] > v[i1]) i1 = e;
        int i2 = -1;
#pragma unroll
        for (int e = 0; e < NUM_EXP; e++)
            if (e != i1 && (i2 < 0 || v[e] > v[i2])) i2 = e;

        float e2 = expf(v[i2] - v[i1]);       // v[i1] >= v[i2]
        float denom = 1.f + e2;
        float g1 = 1.f / denom;
        float g2 = e2 / denom;

#pragma unroll
        for (int e = 0; e < NUM_EXP; e++) g_gates[gwarp * NUM_EXP + e] = 0.f;
        g_gates[gwarp * NUM_EXP + i1] = g1;
        g_gates[gwarp * NUM_EXP + i2] = g2;
        g_topi[gwarp * TOPK + 0] = i1;
        g_topi[gwarp * TOPK + 1] = i2;
        g_pairExpert[gwarp * TOPK + 0] = i1;
        g_pairExpert[gwarp * TOPK + 1] = i2;
        g_pairGate[gwarp * TOPK + 0] = g1;
        g_pairGate[gwarp * TOPK + 1] = g2;
        atomicAdd(&g_counts[i1], 1);
        atomicAdd(&g_counts[i2], 1);
    }
}

// ---------------- scan: 128-aligned segment bases --------------------------
__global__ void scan_kernel() {
    int base = 0;
#pragma unroll
    for (int e = 0; e < NUM_EXP; e++) {
        g_segbase[e] = base;
        g_cursor[e]  = base;
        base += ((g_counts[e] + 127) >> 7) << 7;
    }
    g_segbase[NUM_EXP] = base;
}

// ---------------- scatter pairs into permuted expert-contiguous rows -------
__global__ void scatter_kernel() {
    int p = blockIdx.x * blockDim.x + threadIdx.x;
    if (p >= NPAIR) return;
    int e = g_pairExpert[p];
    int pos = atomicAdd(&g_cursor[e], 1);
    g_permToken[pos] = p >> 1;
    g_permPair[pos]  = p;
    g_permGate[pos]  = g_pairGate[p];
}

// ---------------- GEMM1: h = gelu(x[perm] @ W1[e] + b1[e]) -----------------
__global__ __launch_bounds__(256, 2)
void gemm1_kernel(const float* __restrict__ x,
                  const float* __restrict__ W1,
                  const float* __restrict__ b1) {
    __shared__ float As[BK][BM + 4];
    __shared__ float Bs[BK][BN];

    const int tid = threadIdx.x;
    const int tileN = blockIdx.x;             // 0..31
    const int rowBase = blockIdx.y * BM;

    int expert = 0;
#pragma unroll
    for (int i = 1; i < NUM_EXP; i++) if (g_segbase[i] <= rowBase) expert = i;

    const int ar  = tid >> 2;                 // 0..63
    const int ak4 = (tid & 3) * 4;            // 0,4,8,12
    const int tok0 = g_permToken[rowBase + ar];
    const int tok1 = g_permToken[rowBase + ar + 64];

    const int bn = (tid & 31) * 4;            // 0..124
    const int bk = tid >> 5;                  // 0..7
    const float* Bp = W1 + (size_t)expert * D_MODEL * HIDDEN + (size_t)tileN * BN;

    const int tx = tid & 15, ty = tid >> 4;

    float acc[8][8];
#pragma unroll
    for (int i = 0; i < 8; i++)
#pragma unroll
        for (int j = 0; j < 8; j++) acc[i][j] = 0.f;

    for (int kt = 0; kt < D_MODEL; kt += BK) {
        float4 a0 = make_float4(0.f, 0.f, 0.f, 0.f);
        float4 a1 = make_float4(0.f, 0.f, 0.f, 0.f);
        if (tok0 >= 0) a0 = *(const float4*)(x + (size_t)tok0 * D_MODEL + kt + ak4);
        if (tok1 >= 0) a1 = *(const float4*)(x + (size_t)tok1 * D_MODEL + kt + ak4);
        float4 bv0 = *(const float4*)(Bp + (size_t)(kt + bk) * HIDDEN + bn);
        float4 bv1 = *(const float4*)(Bp + (size_t)(kt + bk + 8) * HIDDEN + bn);

        __syncthreads();
        As[ak4 + 0][ar] = a0.x; As[ak4 + 1][ar] = a0.y;
        As[ak4 + 2][ar] = a0.z; As[ak4 + 3][ar] = a0.w;
        As[ak4 + 0][ar + 64] = a1.x; As[ak4 + 1][ar + 64] = a1.y;
        As[ak4 + 2][ar + 64] = a1.z; As[ak4 + 3][ar + 64] = a1.w;
        *(float4*)&Bs[bk][bn]     = bv0;
        *(float4*)&Bs[bk + 8][bn] = bv1;
        __syncthreads();

#pragma unroll
        for (int k = 0; k < BK; k++) {
            float4 af0 = *(const float4*)&As[k][ty * 4];
            float4 af1 = *(const float4*)&As[k][64 + ty * 4];
            float4 bf0 = *(const float4*)&Bs[k][tx * 4];
            float4 bf1 = *(const float4*)&Bs[k][64 + tx * 4];
            float a[8] = {af0.x, af0.y, af0.z, af0.w, af1.x, af1.y, af1.z, af1.w};
            float b[8] = {bf0.x, bf0.y, bf0.z, bf0.w, bf1.x, bf1.y, bf1.z, bf1.w};
#pragma unroll
            for (int i = 0; i < 8; i++)
#pragma unroll
                for (int j = 0; j < 8; j++) acc[i][j] += a[i] * b[j];
        }
    }

    int rowoff[8], coloff[8];
#pragma unroll
    for (int i = 0; i < 4; i++) {
        rowoff[i] = ty * 4 + i;       rowoff[i + 4] = 64 + ty * 4 + i;
        coloff[i] = tx * 4 + i;       coloff[i + 4] = 64 + tx * 4 + i;
    }
    const float* b1e = b1 + (size_t)expert * HIDDEN + (size_t)tileN * BN;
#pragma unroll
    for (int i = 0; i < 8; i++) {
        size_t rbase = (size_t)(rowBase + rowoff[i]) * HIDDEN + (size_t)tileN * BN;
#pragma unroll
        for (int j = 0; j < 8; j++) {
            float v = acc[i][j] + __ldg(&b1e[coloff[j]]);
            g_h[rbase + coloff[j]] = gelu_exact(v);
        }
    }
}

// ---------------- GEMM2: out[token] += gate * (h @ W2[e] + b2[e]) ----------
__global__ __launch_bounds__(256, 2)
void gemm2_kernel(const float* __restrict__ W2,
                  const float* __restrict__ b2,
                  float* __restrict__ out) {
    __shared__ float As[BK][BM + 4];
    __shared__ float Bs[BK][BN];

    const int tid = threadIdx.x;
    const int tileN = blockIdx.x;             // 0..7 (covers 1000 cols)
    const int rowBase = blockIdx.y * BM;

    int expert = 0;
#pragma unroll
    for (int i = 1; i < NUM_EXP; i++) if (g_segbase[i] <= rowBase) expert = i;

    const int ar  = tid >> 2;
    const int ak4 = (tid & 3) * 4;

    const int bk2  = tid >> 7;                // 0..1
    const int nloc = tid & 127;
    const int nglob = tileN * BN + nloc;
    const float* Bp = W2 + (size_t)expert * HIDDEN * NUM_CLS;

    const int tx = tid & 15, ty = tid >> 4;

    float acc[8][8];
#pragma unroll
    for (int i = 0; i < 8; i++)
#pragma unroll
        for (int j = 0; j < 8; j++) acc[i][j] = 0.f;

    const float* ha0 = g_h + (size_t)(rowBase + ar) * HIDDEN + ak4;
    const float* ha1 = g_h + (size_t)(rowBase + ar + 64) * HIDDEN + ak4;

    for (int kt = 0; kt < HIDDEN; kt += BK) {
        float4 a0 = *(const float4*)(ha0 + kt);
        float4 a1 = *(const float4*)(ha1 + kt);
        float bv[8];
#pragma unroll
        for (int pp = 0; pp < 8; pp++) {
            int kk = kt + pp * 2 + bk2;
            bv[pp] = (nglob < NUM_CLS) ? __ldg(&Bp[(size_t)kk * NUM_CLS + nglob]) : 0.f;
        }

        __syncthreads();
        As[ak4 + 0][ar] = a0.x; As[ak4 + 1][ar] = a0.y;
        As[ak4 + 2][ar] = a0.z; As[ak4 + 3][ar] = a0.w;
        As[ak4 + 0][ar + 64] = a1.x; As[ak4 + 1][ar + 64] = a1.y;
        As[ak4 + 2][ar + 64] = a1.z; As[ak4 + 3][ar + 64] = a1.w;
#pragma unroll
        for (int pp = 0; pp < 8; pp++) Bs[pp * 2 + bk2][nloc] = bv[pp];
        __syncthreads();

#pragma unroll
        for (int k = 0; k < BK; k++) {
            float4 af0 = *(const float4*)&As[k][ty * 4];
            float4 af1 = *(const float4*)&As[k][64 + ty * 4];
            float4 bf0 = *(const float4*)&Bs[k][tx * 4];
            float4 bf1 = *(const float4*)&Bs[k][64 + tx * 4];
            float a[8] = {af0.x, af0.y, af0.z, af0.w, af1.x, af1.y, af1.z, af1.w};
            float b[8] = {bf0.x, bf0.y, bf0.z, bf0.w, bf1.x, bf1.y, bf1.z, bf1.w};
#pragma unroll
            for (int i = 0; i < 8; i++)
#pragma unroll
                for (int j = 0; j < 8; j++) acc[i][j] += a[i] * b[j];
        }
    }

    int rowoff[8], coloff[8];
#pragma unroll
    for (int i = 0; i < 4; i++) {
        rowoff[i] = ty * 4 + i;       rowoff[i + 4] = 64 + ty * 4 + i;
        coloff[i] = tx * 4 + i;       coloff[i + 4] = 64 + tx * 4 + i;
    }
    const float* b2e = b2 + (size_t)expert * NUM_CLS;
#pragma unroll
    for (int i = 0; i < 8; i++) {
        int r = rowBase + rowoff[i];
        int pair = g_permPair[r];
        if (pair < 0) continue;
        int token = pair >> 1;
        float gate = g_permGate[r];
        float* orow = out + (size_t)token * NUM_CLS;
#pragma unroll
        for (int j = 0; j < 8; j++) {
            int cc = tileN * BN + coloff[j];
            if (cc < NUM_CLS) {
                float v = gate * (acc[i][j] + __ldg(&b2e[cc]));
                atomicAdd(&orow[cc], v);   // exactly 2 adds/element: deterministic
            }
        }
    }
}

// ---------------- tail: append gates / topi if the output buffer has room --
__global__ void tail_kernel(float* __restrict__ out, int out_size) {
    int i = blockIdx.x * blockDim.x + threadIdx.x;
    const int OUT0 = BATCH * NUM_CLS;
    if (out_size >= OUT0 + BATCH * NUM_EXP) {
        if (i < BATCH * NUM_EXP)
            out[OUT0 + i] = g_gates[i];
        if (out_size >= OUT0 + BATCH * NUM_EXP + BATCH * TOPK && i < BATCH * TOPK)
            out[OUT0 + BATCH * NUM_EXP + i] = (float)g_topi[i];
    }
}

// ---------------------------------------------------------------------------
extern "C" void kernel_launch(void* const* d_in, const int* in_sizes, int n_in,
                              void* d_out, int out_size) {
    const float* x  = (const float*)d_in[0];
    const float* Wg = (const float*)d_in[1];
    const float* bg = (const float*)d_in[2];
    const float* W1 = (const float*)d_in[3];
    const float* b1 = (const float*)d_in[4];
    const float* W2 = (const float*)d_in[5];
    const float* b2 = (const float*)d_in[6];
    float* out = (float*)d_out;

    cudaMemsetAsync(d_out, 0, (size_t)out_size * sizeof(float));
    init_kernel<<<(CAP + 255) / 256, 256>>>();
    router_kernel<<<BATCH / 8, 256>>>(x, Wg, bg);   // 8 warps/block
    scan_kernel<<<1, 1>>>();
    scatter_kernel<<<(NPAIR + 255) / 256, 256>>>();
    gemm1_kernel<<<dim3(HIDDEN / BN, MAX_TILES), 256>>>(x, W1, b1);
    gemm2_kernel<<<dim3((NUM_CLS + BN - 1) / BN, MAX_TILES), 256>>>(W2, b2, out);
    tail_kernel<<<(BATCH * NUM_EXP + 255) / 256, 256>>>(out, out_size);
}

// round 3
// speedup vs baseline: 2.2244x; 2.2244x over previous
#include <cuda_runtime.h>
#include <cuda_bf16.h>
#include <math.h>
#include <stdint.h>

// ---------------------------------------------------------------------------
// MoE top-2/8: router -> permuted expert segments -> two tf32 mma.sync GEMMs.
// (tcgen05 unavailable: harness compiles via compute_103 virtual arch.)
// ---------------------------------------------------------------------------

#define BATCH      8192
#define D_MODEL    1024
#define HIDDEN     4096
#define NUM_CLS    1000
#define N2PAD      1024                 // W2 N padded
#define NUM_EXP    8
#define TOPK       2
#define NPAIR      (BATCH * TOPK)
#define MAX_TILES  136
#define CAP        (MAX_TILES * 128)

// ---------------- scratch ---------------------------------------------------
__device__ float g_h[(size_t)CAP * HIDDEN];                    // tf32-rounded
__device__ float g_xR[(size_t)BATCH * D_MODEL];                // tf32-rounded x
__device__ float g_W1R[(size_t)NUM_EXP * D_MODEL * HIDDEN];    // tf32 [e][k][n]
__device__ float g_W2R[(size_t)NUM_EXP * HIDDEN * N2PAD];      // tf32 [e][k][n] padded
__device__ float g_gates[BATCH * NUM_EXP];
__device__ int   g_topi[BATCH * TOPK];
__device__ int   g_pairExpert[NPAIR];
__device__ float g_pairGate[NPAIR];
__device__ int   g_counts[NUM_EXP];
__device__ int   g_segbase[NUM_EXP + 1];
__device__ int   g_cursor[NUM_EXP];
__device__ int   g_permToken[CAP];
__device__ int   g_permPair[CAP];
__device__ float g_permGate[CAP];

__device__ __forceinline__ float tf32r(float x) {
    uint32_t o; asm("cvt.rna.tf32.f32 %0, %1;" : "=r"(o) : "f"(x));
    return __uint_as_float(o);
}
__device__ __forceinline__ float gelu_exact(float v) {
    return 0.5f * v * (1.0f + erff(v * 0.70710678118654752f));
}
__device__ __forceinline__ uint32_t smem_u32(const void* p) {
    uint32_t a;
    asm("{ .reg .u64 t; cvta.to.shared.u64 t, %1; cvt.u32.u64 %0, t; }" : "=r"(a) : "l"(p));
    return a;
}

#define CPA16(dst, src)        asm volatile("cp.async.ca.shared.global [%0], [%1], 16;" :: "r"(dst), "l"(src))
#define CPA16_SZ(dst, src, sz) asm volatile("cp.async.ca.shared.global [%0], [%1], 16, %2;" :: "r"(dst), "l"(src), "r"(sz))
#define CPA_COMMIT()           asm volatile("cp.async.commit_group;" ::: "memory")
#define CPA_WAIT1()            asm volatile("cp.async.wait_group 1;" ::: "memory")
#define CPA_WAIT0()            asm volatile("cp.async.wait_group 0;" ::: "memory")

__device__ __forceinline__ void mma_tf32(float* c, const uint32_t* a, const uint32_t* b) {
    asm volatile("mma.sync.aligned.m16n8k8.row.col.f32.tf32.tf32.f32 "
                 "{%0,%1,%2,%3}, {%4,%5,%6,%7}, {%8,%9}, {%0,%1,%2,%3};"
                 : "+f"(c[0]), "+f"(c[1]), "+f"(c[2]), "+f"(c[3])
                 : "r"(a[0]), "r"(a[1]), "r"(a[2]), "r"(a[3]), "r"(b[0]), "r"(b[1]));
}

// ---------------- prep: tf32 rounding passes --------------------------------
__global__ void round_x(const float* __restrict__ x) {
    size_t n4 = (size_t)BATCH * D_MODEL / 4;
    for (size_t i = blockIdx.x * blockDim.x + threadIdx.x; i < n4; i += (size_t)gridDim.x * blockDim.x) {
        float4 v = ((const float4*)x)[i];
        v.x = tf32r(v.x); v.y = tf32r(v.y); v.z = tf32r(v.z); v.w = tf32r(v.w);
        ((float4*)g_xR)[i] = v;
    }
}
__global__ void round_w1(const float* __restrict__ W1) {
    size_t n4 = (size_t)NUM_EXP * D_MODEL * HIDDEN / 4;
    for (size_t i = blockIdx.x * blockDim.x + threadIdx.x; i < n4; i += (size_t)gridDim.x * blockDim.x) {
        float4 v = ((const float4*)W1)[i];
        v.x = tf32r(v.x); v.y = tf32r(v.y); v.z = tf32r(v.z); v.w = tf32r(v.w);
        ((float4*)g_W1R)[i] = v;
    }
}
__global__ void round_w2(const float* __restrict__ W2) {
    size_t rows = (size_t)NUM_EXP * HIDDEN;
    for (size_t i = blockIdx.x * blockDim.x + threadIdx.x; i < rows * N2PAD; i += (size_t)gridDim.x * blockDim.x) {
        size_t r = i / N2PAD; int n = (int)(i % N2PAD);
        g_W2R[i] = (n < NUM_CLS) ? tf32r(W2[r * NUM_CLS + n]) : 0.f;
    }
}

// ---------------- routing ----------------------------------------------------
__global__ void init_kernel() {
    int i = blockIdx.x * blockDim.x + threadIdx.x;
    if (i < CAP) { g_permToken[i] = -1; g_permPair[i] = -1; }
    if (i < NUM_EXP) g_counts[i] = 0;
}

__global__ void router_kernel(const float* __restrict__ x,
                              const float* __restrict__ Wg,
                              const float* __restrict__ bg) {
    int gwarp = (blockIdx.x * blockDim.x + threadIdx.x) >> 5;
    int lane  = threadIdx.x & 31;
    if (gwarp >= BATCH) return;
    const float* xr = x + (size_t)gwarp * D_MODEL;
    float acc[NUM_EXP];
#pragma unroll
    for (int e = 0; e < NUM_EXP; e++) acc[e] = 0.f;
    for (int k0 = lane * 4; k0 < D_MODEL; k0 += 128) {
        float4 xv = *(const float4*)(xr + k0);
        const float* xs = (const float*)&xv;
#pragma unroll
        for (int kk = 0; kk < 4; kk++) {
            const float4* wg = (const float4*)(Wg + (size_t)(k0 + kk) * NUM_EXP);
            float4 w0 = wg[0], w1 = wg[1];
            float xk = xs[kk];
            acc[0] += xk * w0.x; acc[1] += xk * w0.y;
            acc[2] += xk * w0.z; acc[3] += xk * w0.w;
            acc[4] += xk * w1.x; acc[5] += xk * w1.y;
            acc[6] += xk * w1.z; acc[7] += xk * w1.w;
        }
    }
#pragma unroll
    for (int off = 16; off; off >>= 1)
#pragma unroll
        for (int e = 0; e < NUM_EXP; e++)
            acc[e] += __shfl_xor_sync(0xFFFFFFFFu, acc[e], off);
    if (lane == 0) {
        float v[NUM_EXP];
#pragma unroll
        for (int e = 0; e < NUM_EXP; e++) v[e] = acc[e] + bg[e];
        int i1 = 0;
#pragma unroll
        for (int e = 1; e < NUM_EXP; e++) if (v[e] > v[i1]) i1 = e;
        int i2 = -1;
#pragma unroll
        for (int e = 0; e < NUM_EXP; e++)
            if (e != i1 && (i2 < 0 || v[e] > v[i2])) i2 = e;
        float e2 = expf(v[i2] - v[i1]);
        float g1 = 1.f / (1.f + e2), g2 = e2 / (1.f + e2);
#pragma unroll
        for (int e = 0; e < NUM_EXP; e++) g_gates[gwarp * NUM_EXP + e] = 0.f;
        g_gates[gwarp * NUM_EXP + i1] = g1;
        g_gates[gwarp * NUM_EXP + i2] = g2;
        g_topi[gwarp * TOPK + 0] = i1;
        g_topi[gwarp * TOPK + 1] = i2;
        g_pairExpert[gwarp * TOPK + 0] = i1;
        g_pairExpert[gwarp * TOPK + 1] = i2;
        g_pairGate[gwarp * TOPK + 0] = g1;
        g_pairGate[gwarp * TOPK + 1] = g2;
        atomicAdd(&g_counts[i1], 1);
        atomicAdd(&g_counts[i2], 1);
    }
}

__global__ void scan_kernel() {
    int base = 0;
#pragma unroll
    for (int e = 0; e < NUM_EXP; e++) {
        g_segbase[e] = base;
        g_cursor[e]  = base;
        base += ((g_counts[e] + 127) >> 7) << 7;
    }
    g_segbase[NUM_EXP] = base;
}

__global__ void scatter_kernel() {
    int p = blockIdx.x * blockDim.x + threadIdx.x;
    if (p >= NPAIR) return;
    int e = g_pairExpert[p];
    int pos = atomicAdd(&g_cursor[e], 1);
    g_permToken[pos] = p >> 1;
    g_permPair[pos]  = p;
    g_permGate[pos]  = g_pairGate[p];
}

// ---------------- tf32 mma GEMMs --------------------------------------------
// CTA: 256 thr (8 warps, 2Mx4N), tile 128x128, BK=32, double-buffered cp.async.
// A smem stride 36 floats (conflict-free frag loads), B stride 136.
#define AS_STRIDE 36
#define BS_STRIDE 136
#define AS_BYTES  (128 * AS_STRIDE * 4)     // 18432
#define BS_BYTES  (32 * BS_STRIDE * 4)      // 17408
#define SMEM_TOT  (2 * AS_BYTES + 2 * BS_BYTES)  // 71680

struct TileCtx {
    uint32_t aDst[2], bDst[2];      // per-thread smem byte addresses (buf 0/1)
    const float* aSrc;              // row base (k advances)
    const float* bSrc;              // [k][n] base
    int bStrideN;                   // B row stride in floats
    uint32_t aSz;                   // 16 (valid) or 0 (zfill)
};

__device__ __forceinline__ void issue_chunk(const TileCtx& c, int buf, int kt) {
#pragma unroll
    for (int j = 0; j < 4; j++)       // A: 4 x float4 per thread
        CPA16_SZ(c.aDst[buf] + j * 16, c.aSrc + kt + j * 4, c.aSz);
#pragma unroll
    for (int j = 0; j < 4; j++)       // B: 4 x float4 per thread
        CPA16(c.bDst[buf] + j * 16, c.bSrc + (size_t)kt * c.bStrideN + j * 4);
    CPA_COMMIT();
}

__device__ __forceinline__ void mma_tile(const float* As, const float* Bs,
                                         int wr, int wc, int gid, int tig,
                                         float c[4][4][4]) {
#pragma unroll
    for (int ks = 0; ks < 4; ks++) {
        uint32_t b[4][2];
#pragma unroll
        for (int ni = 0; ni < 4; ni++) {
            int col = wc + ni * 8 + gid;
            b[ni][0] = __float_as_uint(Bs[(ks * 8 + tig) * BS_STRIDE + col]);
            b[ni][1] = __float_as_uint(Bs[(ks * 8 + tig + 4) * BS_STRIDE + col]);
        }
#pragma unroll
        for (int mi = 0; mi < 4; mi++) {
            int r0 = wr + mi * 16 + gid;
            uint32_t a[4];
            a[0] = __float_as_uint(As[r0 * AS_STRIDE + ks * 8 + tig]);
            a[1] = __float_as_uint(As[(r0 + 8) * AS_STRIDE + ks * 8 + tig]);
            a[2] = __float_as_uint(As[r0 * AS_STRIDE + ks * 8 + tig + 4]);
            a[3] = __float_as_uint(As[(r0 + 8) * AS_STRIDE + ks * 8 + tig + 4]);
#pragma unroll
            for (int ni = 0; ni < 4; ni++) mma_tf32(c[mi][ni], a, b[ni]);
        }
    }
}

__device__ __forceinline__ void setup_ctx(TileCtx& c, char* smem, int tid) {
    uint32_t sb = smem_u32(smem);
    int am = tid >> 1, ak = (tid & 1) * 16;            // A: row, k-offset
    int bk = tid >> 3, bn = (tid & 7) * 16;            // B: k-row, n-offset
    c.aDst[0] = sb + (am * AS_STRIDE + ak) * 4;
    c.aDst[1] = c.aDst[0] + AS_BYTES;
    c.bDst[0] = sb + 2 * AS_BYTES + (bk * BS_STRIDE + bn) * 4;
    c.bDst[1] = c.bDst[0] + BS_BYTES;
    c.aSz = 16;
}

__global__ __launch_bounds__(256, 2)
void gemm1_mma(const float* __restrict__ b1) {
    extern __shared__ __align__(16) char smem[];
    const int tid = threadIdx.x, wid = tid >> 5, lane = tid & 31;
    const int rowBase = blockIdx.x * 128, nBase = blockIdx.y * 128;
    if (rowBase >= g_segbase[NUM_EXP]) return;
    int expert = 0;
#pragma unroll
    for (int i = 1; i < NUM_EXP; i++) if (g_segbase[i] <= rowBase) expert = i;

    TileCtx ctx; setup_ctx(ctx, smem, tid);
    const int am = tid >> 1, ak = (tid & 1) * 16;
    const int bk = tid >> 3, bn = (tid & 7) * 16;
    const int tok = g_permToken[rowBase + am];
    ctx.aSrc = g_xR + (size_t)(tok < 0 ? 0 : tok) * D_MODEL + ak;
    ctx.aSz  = tok < 0 ? 0u : 16u;
    ctx.bSrc = g_W1R + (size_t)expert * D_MODEL * HIDDEN + (size_t)bk * HIDDEN + nBase + bn;
    ctx.bStrideN = HIDDEN;

    const int gid = lane >> 2, tig = lane & 3;
    const int wr = (wid >> 2) * 64, wc = (wid & 3) * 32;
    float c[4][4][4];
#pragma unroll
    for (int mi = 0; mi < 4; mi++)
#pragma unroll
        for (int ni = 0; ni < 4; ni++)
#pragma unroll
            for (int q = 0; q < 4; q++) c[mi][ni][q] = 0.f;

    const float* As = (const float*)smem;
    const float* Bs = (const float*)(smem + 2 * AS_BYTES);
    const int NIT = D_MODEL / 32;

    issue_chunk(ctx, 0, 0);
    for (int it = 0; it < NIT; ++it) {
        if (it + 1 < NIT) { issue_chunk(ctx, (it + 1) & 1, (it + 1) * 32); CPA_WAIT1(); }
        else CPA_WAIT0();
        __syncthreads();
        int buf = it & 1;
        mma_tile(As + buf * (AS_BYTES / 4), Bs + buf * (BS_BYTES / 4), wr, wc, gid, tig, c);
        __syncthreads();
    }

    const float* bb = b1 + (size_t)expert * HIDDEN + nBase;
#pragma unroll
    for (int mi = 0; mi < 4; mi++) {
        int r0 = rowBase + wr + mi * 16 + gid;
#pragma unroll
        for (int ni = 0; ni < 4; ni++) {
            int col = wc + ni * 8 + tig * 2;
            float bias0 = __ldg(bb + col), bias1 = __ldg(bb + col + 1);
            float2 v0, v1;
            v0.x = tf32r(gelu_exact(c[mi][ni][0] + bias0));
            v0.y = tf32r(gelu_exact(c[mi][ni][1] + bias1));
            v1.x = tf32r(gelu_exact(c[mi][ni][2] + bias0));
            v1.y = tf32r(gelu_exact(c[mi][ni][3] + bias1));
            *(float2*)(g_h + (size_t)r0 * HIDDEN + nBase + col) = v0;
            *(float2*)(g_h + (size_t)(r0 + 8) * HIDDEN + nBase + col) = v1;
        }
    }
}

__global__ __launch_bounds__(256, 2)
void gemm2_mma(const float* __restrict__ b2, float* __restrict__ out) {
    extern __shared__ __align__(16) char smem[];
    const int tid = threadIdx.x, wid = tid >> 5, lane = tid & 31;
    const int rowBase = blockIdx.x * 128, nBase = blockIdx.y * 128;
    if (rowBase >= g_segbase[NUM_EXP]) return;
    int expert = 0;
#pragma unroll
    for (int i = 1; i < NUM_EXP; i++) if (g_segbase[i] <= rowBase) expert = i;

    TileCtx ctx; setup_ctx(ctx, smem, tid);
    const int am = tid >> 1, ak = (tid & 1) * 16;
    const int bk = tid >> 3, bn = (tid & 7) * 16;
    ctx.aSrc = g_h + (size_t)(rowBase + am) * HIDDEN + ak;
    ctx.bSrc = g_W2R + (size_t)expert * HIDDEN * N2PAD + (size_t)bk * N2PAD + nBase + bn;
    ctx.bStrideN = N2PAD;

    const int gid = lane >> 2, tig = lane & 3;
    const int wr = (wid >> 2) * 64, wc = (wid & 3) * 32;
    float c[4][4][4];
#pragma unroll
    for (int mi = 0; mi < 4; mi++)
#pragma unroll
        for (int ni = 0; ni < 4; ni++)
#pragma unroll
            for (int q = 0; q < 4; q++) c[mi][ni][q] = 0.f;

    const float* As = (const float*)smem;
    const float* Bs = (const float*)(smem + 2 * AS_BYTES);
    const int NIT = HIDDEN / 32;

    issue_chunk(ctx, 0, 0);
    for (int it = 0; it < NIT; ++it) {
        if (it + 1 < NIT) { issue_chunk(ctx, (it + 1) & 1, (it + 1) * 32); CPA_WAIT1(); }
        else CPA_WAIT0();
        __syncthreads();
        int buf = it & 1;
        mma_tile(As + buf * (AS_BYTES / 4), Bs + buf * (BS_BYTES / 4), wr, wc, gid, tig, c);
        __syncthreads();
    }

    const float* bb = b2 + (size_t)expert * NUM_CLS;
#pragma unroll
    for (int mi = 0; mi < 4; mi++) {
        int r0 = rowBase + wr + mi * 16 + gid;
#pragma unroll
        for (int half = 0; half < 2; half++) {
            int r = r0 + half * 8;
            int pair = g_permPair[r];
            if (pair < 0) continue;
            float gate = g_permGate[r];
            float* orow = out + (size_t)(pair >> 1) * NUM_CLS;
#pragma unroll
            for (int ni = 0; ni < 4; ni++) {
                int col = nBase + wc + ni * 8 + tig * 2;
                if (col < NUM_CLS)
                    atomicAdd(orow + col, gate * (c[mi][ni][half * 2 + 0] + __ldg(bb + col)));
                if (col + 1 < NUM_CLS)
                    atomicAdd(orow + col + 1, gate * (c[mi][ni][half * 2 + 1] + __ldg(bb + col + 1)));
            }
        }
    }
}

// ---------------- tail -------------------------------------------------------
__global__ void tail_kernel(float* __restrict__ out, int out_size) {
    int i = blockIdx.x * blockDim.x + threadIdx.x;
    const int OUT0 = BATCH * NUM_CLS;
    if (out_size >= OUT0 + BATCH * NUM_EXP) {
        if (i < BATCH * NUM_EXP)
            out[OUT0 + i] = g_gates[i];
        if (out_size >= OUT0 + BATCH * NUM_EXP + BATCH * TOPK && i < BATCH * TOPK)
            out[OUT0 + BATCH * NUM_EXP + i] = (float)g_topi[i];
    }
}

// ---------------------------------------------------------------------------
extern "C" void kernel_launch(void* const* d_in, const int* in_sizes, int n_in,
                              void* d_out, int out_size) {
    const float* x  = (const float*)d_in[0];
    const float* Wg = (const float*)d_in[1];
    const float* bg = (const float*)d_in[2];
    const float* W1 = (const float*)d_in[3];
    const float* b1 = (const float*)d_in[4];
    const float* W2 = (const float*)d_in[5];
    const float* b2 = (const float*)d_in[6];
    float* out = (float*)d_out;

    cudaFuncSetAttribute(gemm1_mma, cudaFuncAttributeMaxDynamicSharedMemorySize, SMEM_TOT);
    cudaFuncSetAttribute(gemm2_mma, cudaFuncAttributeMaxDynamicSharedMemorySize, SMEM_TOT);

    cudaMemsetAsync(d_out, 0, (size_t)out_size * sizeof(float));
    init_kernel<<<(CAP + 255) / 256, 256>>>();
    round_x<<<512, 256>>>(x);
    round_w1<<<2048, 256>>>(W1);
    round_w2<<<2048, 256>>>(W2);
    router_kernel<<<BATCH / 8, 256>>>(x, Wg, bg);
    scan_kernel<<<1, 1>>>();
    scatter_kernel<<<(NPAIR + 255) / 256, 256>>>();
    gemm1_mma<<<dim3(MAX_TILES, HIDDEN / 128), 256, SMEM_TOT>>>(b1);
    gemm2_mma<<<dim3(MAX_TILES, N2PAD / 128), 256, SMEM_TOT>>>(b2, out);
    tail_kernel<<<(BATCH * NUM_EXP + 255) / 256, 256>>>(out, out_size);
}